// round 16
// baseline (speedup 1.0000x reference)
#include <cuda_runtime.h>
#include <cuda_bf16.h>
#include <cuda_fp16.h>
#include <cstdint>

// Problem constants
#define B_  64
#define T_  256
#define E_  512
#define U_  1024
#define N3_ 3072

#define NBLK 128          // scan grid (1 block/SM, all resident)
#define UPB  8            // GRU units per scan block
#define SCTH 256          // 8 warps: 4 k-teams x 2 m-halves

#define WLO_SCALE 1024.0f  // keeps fp16 W-residuals out of subnormal range

// ---- scan smem layout (bytes) ----
#define WPLANE 49536                 // [24 n][1032 halves] stride 2064B
#define OFF_W    0                   // 2 planes (hi, lo*1024)
#define OFF_RECS 99072               // [4 teams][24 n][68 floats]
#define RECF     1632                // floats per team
#define OFF_BHS  125184
#define SCAN_SMEM 125312

// ---- xproj smem layout (bytes) ----
#define XP_TOK  0                    // 128 ints
#define XP_A    512                  // [3 stages][2 planes][128 rows * 48B]
#define XP_APLANE 6144
#define XP_B    37376                // [3 stages][2 planes][64 rows * 48B]
#define XP_BPLANE 3072
#define XP_SMEM 55808

// ----------------- device scratch (no allocations allowed) -----------------
__device__ float g_xproj[(size_t)B_ * T_ * N3_];          // [B*T][3U] incl. bx
// h (fp16) in MMA A-fragment order, TRIPLE buffered: [buf][slot u32]
// slot = ((K*4 + mt)*32 + lane)*4 + reg,  K=k>>4 (64), mt=row>>4 (4)
__device__ uint32_t g_hA[3][32768];
__device__ unsigned g_cflag[8];     // per-chunk producer counters (monotonic)
__device__ __nv_bfloat16 g_embh[(size_t)32000 * E_];      // [tok][k]
__device__ __nv_bfloat16 g_embl[(size_t)32000 * E_];
__device__ __nv_bfloat16 g_wxh[(size_t)N3_ * E_];         // TRANSPOSED [n][k]
__device__ __nv_bfloat16 g_wxl[(size_t)N3_ * E_];

// ----------------- ptx helpers ---------------------------------------------
__device__ __forceinline__ uint32_t smem_u32(const void* p) {
    uint32_t a;
    asm("{ .reg .u64 t; cvta.to.shared.u64 t, %1; cvt.u32.u64 %0, t; }"
        : "=r"(a) : "l"(p));
    return a;
}
__device__ __forceinline__ void ldsm_x4(uint32_t* r, uint32_t addr) {
    asm volatile("ldmatrix.sync.aligned.m8n8.x4.shared.b16 {%0,%1,%2,%3}, [%4];"
                 : "=r"(r[0]), "=r"(r[1]), "=r"(r[2]), "=r"(r[3]) : "r"(addr));
}
__device__ __forceinline__ void mma_bf16(float* d, const uint32_t* a,
                                         const uint32_t* b) {
    asm volatile(
        "mma.sync.aligned.m16n8k16.row.col.f32.bf16.bf16.f32 "
        "{%0,%1,%2,%3}, {%4,%5,%6,%7}, {%8,%9}, {%0,%1,%2,%3};"
        : "+f"(d[0]), "+f"(d[1]), "+f"(d[2]), "+f"(d[3])
        : "r"(a[0]), "r"(a[1]), "r"(a[2]), "r"(a[3]), "r"(b[0]), "r"(b[1]));
}
__device__ __forceinline__ void mma_f16(float* d, const uint32_t* a,
                                        const uint32_t* b) {
    asm volatile(
        "mma.sync.aligned.m16n8k16.row.col.f32.f16.f16.f32 "
        "{%0,%1,%2,%3}, {%4,%5,%6,%7}, {%8,%9}, {%0,%1,%2,%3};"
        : "+f"(d[0]), "+f"(d[1]), "+f"(d[2]), "+f"(d[3])
        : "r"(a[0]), "r"(a[1]), "r"(a[2]), "r"(a[3]), "r"(b[0]), "r"(b[1]));
}
__device__ __forceinline__ void cpa16(uint32_t dst, const void* src) {
    asm volatile("cp.async.cg.shared.global [%0], [%1], 16;"
                 :: "r"(dst), "l"(src) : "memory");
}
__device__ __forceinline__ void cpa_commit() {
    asm volatile("cp.async.commit_group;" ::: "memory");
}
template <int N>
__device__ __forceinline__ void cpa_wait() {
    asm volatile("cp.async.wait_group %0;" :: "n"(N) : "memory");
}

// wait until chunk c's producers for this step have arrived
__device__ __forceinline__ void wait_chunk(int c, unsigned target, int lane) {
    if (lane == 0) {
        volatile unsigned* f = (volatile unsigned*)&g_cflag[c];
        while (*f < target) { }
    }
    __syncwarp();
}

// load one chunk's A fragments (4 x LDG.128) straight into registers
__device__ __forceinline__ void lda_chunk(uint4* dst, int c, int tm, int mh,
                                          int lane, const uint4* h0) {
#pragma unroll
    for (int mtl = 0; mtl < 2; mtl++)
#pragma unroll
        for (int ks = 0; ks < 2; ks++) {
            int idx = (((c * 8 + tm * 2 + ks) * 4) + (2 * mh + mtl)) * 32 + lane;
            dst[mtl * 2 + ks] = __ldcg(h0 + idx);
        }
}

// ----------------- init: reset flags + h0 -> fragment-ordered fp16 ---------
__global__ void k_init(const float* __restrict__ hidden) {
    int idx = blockIdx.x * blockDim.x + threadIdx.x;
    if (idx < 8) g_cflag[idx] = 0u;
    if (idx < B_ * U_) {
        int row = idx >> 10;
        int k = idx & (U_ - 1);
        __half h = __float2half_rn(hidden[idx]);
        int K = k >> 4, klo = k & 15, mt = row >> 4, r = row & 15;
        int lane = (r & 7) * 4 + ((klo >> 1) & 3);
        int reg = (r >> 3) + 2 * (klo >> 3);
        int slot = ((K * 4 + mt) * 32 + lane) * 4 + reg;
        reinterpret_cast<unsigned short*>(&g_hA[0][slot])[klo & 1] =
            __half_as_ushort(h);
    }
}

// ----------------- prep: split emb (as-is) and Wx (TRANSPOSED) -------------
__global__ void k_prep(const float* __restrict__ emb,
                       const float* __restrict__ Wx) {
    const size_t n1 = (size_t)32000 * E_;
    const size_t n2 = (size_t)N3_ * E_;
    for (size_t i = (size_t)blockIdx.x * blockDim.x + threadIdx.x; i < n1 + n2;
         i += (size_t)gridDim.x * blockDim.x) {
        if (i < n1) {
            float v = emb[i];
            __nv_bfloat16 hi = __float2bfloat16(v);
            g_embh[i] = hi;
            g_embl[i] = __float2bfloat16(v - __bfloat162float(hi));
        } else {
            size_t j = i - n1;          // j = n * E + k  (transposed layout)
            int n = (int)(j >> 9);
            int k = (int)(j & (E_ - 1));
            float v = Wx[(size_t)k * N3_ + n];
            __nv_bfloat16 hi = __float2bfloat16(v);
            g_wxh[j] = hi;
            g_wxl[j] = __float2bfloat16(v - __bfloat162float(hi));
        }
    }
}

// ----------------- kernel 1: tensor-core x_proj (round-8 proven) -----------
__global__ __launch_bounds__(256, 2)
void k_xproj_tc(const int* __restrict__ tokens, const float* __restrict__ bx) {
    extern __shared__ char xs[];
    const uint32_t sb = smem_u32(xs);
    const int tid = threadIdx.x;
    const int wid = tid >> 5;
    const int lane = tid & 31;
    const int n0 = blockIdx.x * 64;
    const int m0 = blockIdx.y * 128;

    int* toks = reinterpret_cast<int*>(xs + XP_TOK);
    if (tid < 128) toks[tid] = tokens[m0 + tid];
    __syncthreads();

    const int arow = tid >> 1, aseg = tid & 1;
    const size_t aoff = (size_t)toks[arow] * E_ + aseg * 8;
    const uint32_t adst = sb + XP_A + arow * 48 + aseg * 16;
    const int bplane = tid >> 7, b2 = tid & 127;
    const int brow = b2 >> 1, bseg = b2 & 1;
    const __nv_bfloat16* wsrc =
        (bplane ? g_wxl : g_wxh) + (size_t)(n0 + brow) * E_ + bseg * 8;
    const uint32_t bdst =
        sb + XP_B + bplane * XP_BPLANE + brow * 48 + bseg * 16;

#define XP_ISSUE(s, buf)                                               \
    {                                                                  \
        int k0_ = (s) * 16;                                            \
        cpa16(adst + (buf) * 12288, g_embh + aoff + k0_);              \
        cpa16(adst + (buf) * 12288 + XP_APLANE, g_embl + aoff + k0_);  \
        cpa16(bdst + (buf) * 6144, wsrc + k0_);                        \
        cpa_commit();                                                  \
    }

    const int mw = wid & 3, nw = wid >> 2;
    float acc[2][4][4];
#pragma unroll
    for (int mt = 0; mt < 2; mt++)
#pragma unroll
        for (int nt = 0; nt < 4; nt++)
#pragma unroll
            for (int j = 0; j < 4; j++) acc[mt][nt][j] = 0.f;

    const uint32_t a_off =
        (uint32_t)((mw * 32 + (lane & 15)) * 48 + ((lane >> 4) << 3) * 2);
    const uint32_t b_off =
        (uint32_t)((nw * 32 + (lane & 7) + ((lane >> 4) << 3)) * 48 +
                   (((lane >> 3) & 1) << 4));

    XP_ISSUE(0, 0);
    XP_ISSUE(1, 1);

    for (int s = 0; s < 32; s++) {
        const int buf = s % 3;
        cpa_wait<1>();
        __syncthreads();

        const uint32_t ab = sb + XP_A + buf * 12288 + a_off;
        const uint32_t bb = sb + XP_B + buf * 6144 + b_off;
        uint32_t ah[2][4], al[2][4], bhf[2][4], blf[2][4];
        ldsm_x4(ah[0], ab);
        ldsm_x4(ah[1], ab + 16 * 48);
        ldsm_x4(al[0], ab + XP_APLANE);
        ldsm_x4(al[1], ab + XP_APLANE + 16 * 48);
        ldsm_x4(bhf[0], bb);
        ldsm_x4(bhf[1], bb + 16 * 48);
        ldsm_x4(blf[0], bb + XP_BPLANE);
        ldsm_x4(blf[1], bb + XP_BPLANE + 16 * 48);

#pragma unroll
        for (int mt = 0; mt < 2; mt++)
#pragma unroll
            for (int nt = 0; nt < 4; nt++) {
                const uint32_t* fh = &bhf[nt >> 1][(nt & 1) * 2];
                const uint32_t* fl = &blf[nt >> 1][(nt & 1) * 2];
                mma_bf16(acc[mt][nt], ah[mt], fh);
                mma_bf16(acc[mt][nt], al[mt], fh);
                mma_bf16(acc[mt][nt], ah[mt], fl);
            }

        if (s + 2 < 32) XP_ISSUE(s + 2, (s + 2) % 3);
    }

    const int r0 = m0 + mw * 32 + (lane >> 2);
    const int c0 = n0 + nw * 32 + (lane & 3) * 2;
#pragma unroll
    for (int mt = 0; mt < 2; mt++)
#pragma unroll
        for (int nt = 0; nt < 4; nt++) {
            int rr = r0 + mt * 16, cc = c0 + nt * 8;
            float b0 = bx[cc], b1 = bx[cc + 1];
            float2 v0 = make_float2(acc[mt][nt][0] + b0, acc[mt][nt][1] + b1);
            float2 v1 = make_float2(acc[mt][nt][2] + b0, acc[mt][nt][3] + b1);
            *reinterpret_cast<float2*>(&g_xproj[(size_t)rr * N3_ + cc]) = v0;
            *reinterpret_cast<float2*>(&g_xproj[(size_t)(rr + 8) * N3_ + cc]) = v1;
        }
#undef XP_ISSUE
}

// ----------------- kernel 2: persistent mma.sync GRU scan ------------------
// Chunk-granular flow control: chunk c of h is produced by blocks
// [16c,16c+16); consumers spin on g_cflag[c] >= 16*t per chunk instead of a
// full grid barrier. h triple-buffered (read t%3, write (t+1)%3) to cover
// the WAR hazard. fp16 h single plane; Wh split-fp16 with scaled lo.
__global__ __launch_bounds__(SCTH, 1)
void k_scan(const float* __restrict__ Wh, const float* __restrict__ bh,
            const float* __restrict__ hidden, float* __restrict__ out) {
    extern __shared__ __align__(128) char smem[];
    const uint32_t sb = smem_u32(smem);
    const int tid = threadIdx.x;
    const int wid = tid >> 5;
    const int lane = tid & 31;
    const int u0 = blockIdx.x * UPB;
    const int c_own = blockIdx.x >> 4;   // chunk this block produces

    // ---- stage Wh columns as fp16 hi + scaled lo ----
    for (int idx = tid; idx < 24 * 1024; idx += SCTH) {
        int n = idx >> 10, k = idx & 1023;
        int col = (n >> 3) * U_ + u0 + (n & 7);
        float w = Wh[(size_t)k * N3_ + col];
        __half whi = __float2half_rn(w);
        __half wlo = __float2half_rn((w - __half2float(whi)) * WLO_SCALE);
        int off = n * 2064 + k * 2;
        *reinterpret_cast<__half*>(smem + OFF_W + off) = whi;
        *reinterpret_cast<__half*>(smem + OFF_W + WPLANE + off) = wlo;
    }
    float* recs = reinterpret_cast<float*>(smem + OFF_RECS);
    float* bhs = reinterpret_cast<float*>(smem + OFF_BHS);
    if (tid < 24) bhs[tid] = bh[(tid >> 3) * U_ + u0 + (tid & 7)];

    // ---- warp geometry: 4 k-teams x 2 m-halves ----
    const int tm = wid & 3;          // k-team: 32 k per 128-chunk
    const int mh = wid >> 2;         // m-half: rows mh*32 .. +31

    uint32_t b_off[3];
#pragma unroll
    for (int nt = 0; nt < 3; nt++)
        b_off[nt] = (uint32_t)((nt * 8 + (lane & 7)) * 2064 +
                               (((lane >> 3) & 3) << 4));

    // gate mapping & producer slot (fragment-ordered h write)
    const int grow = tid >> 2;
    const int gup = (tid & 3) << 1;
    const int kk = u0 + gup;
    const int slot_p = ((((kk >> 4) * 4 + (grow >> 4)) * 32 +
                         ((grow & 7) * 4 + (((kk & 15) >> 1) & 3))) * 4) +
                       (((grow & 15) >> 3) + 2 * ((kk & 15) >> 3));

    float hprev[2];
    {
        const float2 h2 = *reinterpret_cast<const float2*>(
            &hidden[(size_t)grow * U_ + u0 + gup]);
        hprev[0] = h2.x;
        hprev[1] = h2.y;
    }
    __syncthreads();

    for (int t = 0; t < T_; t++) {
        const unsigned tgt = 16u * (unsigned)t;
        const uint4* hA0 = reinterpret_cast<const uint4*>(g_hA[t % 3]);

        // hoisted gate xp loads (independent of h -> issue first)
        float2 xz2, xr2, xh2;
        {
            const float* xp =
                &g_xproj[((size_t)grow * T_ + t) * N3_ + u0 + gup];
            xz2 = __ldg(reinterpret_cast<const float2*>(xp));
            xr2 = __ldg(reinterpret_cast<const float2*>(xp + U_));
            xh2 = __ldg(reinterpret_cast<const float2*>(xp + 2 * U_));
        }

        float acc[2][3][4], acc2[2][3][4];
#pragma unroll
        for (int mt = 0; mt < 2; mt++)
#pragma unroll
            for (int nt = 0; nt < 3; nt++)
#pragma unroll
                for (int j = 0; j < 4; j++) {
                    acc[mt][nt][j] = 0.f;
                    acc2[mt][nt][j] = 0.f;
                }

        uint4 fa[3][4];                       // 2-deep A fragment pipeline
        wait_chunk(0, tgt, lane);
        lda_chunk(fa[0], 0, tm, mh, lane, hA0);
        wait_chunk(1, tgt, lane);
        lda_chunk(fa[1], 1, tm, mh, lane, hA0);

#pragma unroll
        for (int c = 0; c < 8; c++) {
            if (c < 6) {
                wait_chunk(c + 2, tgt, lane);
                lda_chunk(fa[(c + 2) % 3], c + 2, tm, mh, lane, hA0);
            }

            const uint32_t bbase =
                sb + OFF_W + (uint32_t)(c * 128 + tm * 32) * 2;
            uint32_t bhf[3][4], blf[3][4];
#pragma unroll
            for (int nt = 0; nt < 3; nt++) {
                ldsm_x4(bhf[nt], bbase + b_off[nt]);
                ldsm_x4(blf[nt], bbase + WPLANE + b_off[nt]);
            }
            const uint4* cur = fa[c % 3];
#pragma unroll
            for (int mtl = 0; mtl < 2; mtl++)
#pragma unroll
                for (int ks = 0; ks < 2; ks++) {
                    const uint32_t* ah =
                        reinterpret_cast<const uint32_t*>(&cur[mtl * 2 + ks]);
#pragma unroll
                    for (int nt = 0; nt < 3; nt++) {
                        mma_f16(acc[mtl][nt], ah, &bhf[nt][ks * 2]);
                        mma_f16(acc2[mtl][nt], ah, &blf[nt][ks * 2]);
                    }
                }
        }

        // write team-partial rec sums (combine scaled-lo): recs[tm][n][row]
        {
            float* recT = recs + tm * RECF;
            int n = 2 * (lane & 3);
            int rowb = mh * 32 + (lane >> 2);
            const float inv = 1.0f / WLO_SCALE;
#pragma unroll
            for (int mt = 0; mt < 2; mt++) {
                int row = rowb + mt * 16;
#pragma unroll
                for (int nt = 0; nt < 3; nt++) {
                    int nb_ = nt * 8 + n;
                    recT[nb_ * 68 + row] =
                        acc[mt][nt][0] + acc2[mt][nt][0] * inv;
                    recT[(nb_ + 1) * 68 + row] =
                        acc[mt][nt][1] + acc2[mt][nt][1] * inv;
                    recT[nb_ * 68 + row + 8] =
                        acc[mt][nt][2] + acc2[mt][nt][2] * inv;
                    recT[(nb_ + 1) * 68 + row + 8] =
                        acc[mt][nt][3] + acc2[mt][nt][3] * inv;
                }
            }
        }
        __syncthreads();

        // gates: each thread does (grow, units gup, gup+1)
        float hn[2];
        {
#pragma unroll
            for (int j = 0; j < 2; j++) {
                int uu = gup + j;
                float rz = bhs[uu], rr = bhs[8 + uu], rh = bhs[16 + uu];
#pragma unroll
                for (int tt = 0; tt < 4; tt++) {
                    rz += recs[tt * RECF + uu * 68 + grow];
                    rr += recs[tt * RECF + (8 + uu) * 68 + grow];
                    rh += recs[tt * RECF + (16 + uu) * 68 + grow];
                }
                float xz = j ? xz2.y : xz2.x;
                float xr = j ? xr2.y : xr2.x;
                float xh = j ? xh2.y : xh2.x;
                float z = 1.f / (1.f + __expf(-(xz + rz)));
                float r = 1.f / (1.f + __expf(-(xr + rr)));
                float ca = xh + r * rh;
                float cand = 1.f - 2.f / (__expf(2.f * ca) + 1.f);
                hn[j] = z * hprev[j] + (1.f - z) * cand;
                hprev[j] = hn[j];
            }
            // store fp16 h in fragment order to write buffer (t+1)%3
            __half f0 = __float2half_rn(hn[0]);
            __half f1 = __float2half_rn(hn[1]);
            unsigned ph = ((unsigned)__half_as_ushort(f1) << 16) |
                          __half_as_ushort(f0);
            __stcg(&g_hA[(t + 1) % 3][slot_p], ph);
        }

        // release: h stores visible, then arrive on own chunk flag
        __threadfence();
        __syncthreads();
        if (tid == 0) atomicAdd(&g_cflag[c_own], 1u);

        // out stores (no ordering requirement)
        {
            float2 o2 = make_float2(hn[0], hn[1]);
            *reinterpret_cast<float2*>(
                &out[((size_t)grow * T_ + t) * U_ + u0 + gup]) = o2;
            if (t == T_ - 1)
                *reinterpret_cast<float2*>(
                    &out[(size_t)B_ * T_ * U_ + (size_t)grow * U_ + u0 + gup]) = o2;
        }
    }
}

// ----------------- launch ---------------------------------------------------
extern "C" void kernel_launch(void* const* d_in, const int* in_sizes, int n_in,
                              void* d_out, int out_size) {
    const int* tokens = (const int*)d_in[0];
    const float* hidden = (const float*)d_in[1];
    const float* emb = (const float*)d_in[2];
    const float* Wx = (const float*)d_in[3];
    const float* bx = (const float*)d_in[4];
    const float* Wh = (const float*)d_in[5];
    const float* bh = (const float*)d_in[6];
    float* out = (float*)d_out;
    (void)in_sizes; (void)n_in; (void)out_size;

    cudaFuncSetAttribute(k_scan, cudaFuncAttributeMaxDynamicSharedMemorySize,
                         SCAN_SMEM);
    cudaFuncSetAttribute(k_xproj_tc, cudaFuncAttributeMaxDynamicSharedMemorySize,
                         XP_SMEM);

    k_init<<<(B_ * U_ + 255) / 256, 256>>>(hidden);
    k_prep<<<1024, 256>>>(emb, Wx);
    dim3 gx(N3_ / 64, (B_ * T_) / 128);
    k_xproj_tc<<<gx, 256, XP_SMEM>>>(tokens, bx);
    k_scan<<<NBLK, SCTH, SCAN_SMEM>>>(Wh, bh, hidden, out);
}